// round 15
// baseline (speedup 1.0000x reference)
#include <cuda_runtime.h>

// PGJANET recurrent scan: B=256, T=2048, H=64, O=2.
// R14 base, restructured to 3 barriers/step:
//  seg1: ph1 partial dots (all threads, 160 FMA) + y-stage1 hidden on warps 6-7
//  seg2: u-finalize (warps 0-3) || y-finish (warp 5, 4 lanes)
//  seg3: FUSED f/g u-dot + h-finalize on ALL threads: lane pair per (e,j),
//        even lane = f (64 FMA + sigmoid), odd lane = g (64 FMA + tanh),
//        single shfl_xor(1) exchange, even lane writes h.
// MUFU transcendentals; x-scalars pipelined one step ahead; scalar FFMA.

#define TB 2048

__device__ __forceinline__ float tanhmufu(float v) {
    float r; asm("tanh.approx.f32 %0, %1;" : "=f"(r) : "f"(v)); return r;
}
__device__ __forceinline__ float sigmufu(float v) {
    return fmaf(0.5f, tanhmufu(0.5f * v), 0.5f);
}

__global__ void __launch_bounds__(256, 1)
pgjanet_kernel(const float* __restrict__ x,
               const float* __restrict__ h0,
               const float* __restrict__ Wa,  const float* __restrict__ ba,
               const float* __restrict__ Wp1, const float* __restrict__ bp1,
               const float* __restrict__ Wp2, const float* __restrict__ bp2,
               const float* __restrict__ Wf,  const float* __restrict__ bf,
               const float* __restrict__ Wg,  const float* __restrict__ bg,
               const float* __restrict__ Wo,  const float* __restrict__ bo,
               float* __restrict__ out)
{
    __shared__ __align__(16) float2 xb[2][TB];        // 32 KB
    __shared__ __align__(16) float hbuf[2][64];
    __shared__ __align__(16) float ubuf[2][64];
    __shared__ __align__(16) float part[2][5][4][64]; // [elem][gate][slice][unit]
    __shared__ __align__(16) float ypart[2][2][8];    // [elem][out][8 partials]

    const int tid  = threadIdx.x;
    const int lane = tid & 31;
    const int wid  = tid >> 5;
    const int j    = tid & 63;      // ph1: hidden unit
    const int s    = tid >> 6;      // ph1: k-slice 0..3
    const int b0   = blockIdx.x * 2;

    // fused-seg3 mapping: lane pair per (e2, j2)
    const int pr   = tid >> 1;      // pair 0..127
    const int e2   = pr >> 6;       // elem
    const int j2   = pr & 63;       // unit
    const int isg  = tid & 1;       // 0 = f(sigmoid), 1 = g(tanh)

    // ---- ph1 weights in registers (80 floats) ----
    float wa[16], wp1[16], wp2[16], wfh[16], wgh[16];
    {
        const float* A = Wa  + j * 65 + s * 16;
        const float* P = Wp1 + j * 65 + s * 16;
        const float* Q = Wp2 + j * 65 + s * 16;
        const float* F = Wf  + j * 128 + s * 16;
        const float* G = Wg  + j * 128 + s * 16;
        #pragma unroll
        for (int i = 0; i < 16; i++) {
            wa[i]  = A[i];  wp1[i] = P[i];  wp2[i] = Q[i];
            wfh[i] = F[i];  wgh[i] = G[i];
        }
    }
    // ---- fused-seg3 weights: full u-half row of Wf (even) or Wg (odd) ----
    float wrow[64];
    {
        const float* R = (isg ? Wg : Wf) + j2 * 128 + 64;
        #pragma unroll
        for (int i = 0; i < 64; i++) wrow[i] = R[i];
    }
    const float bias2 = isg ? bg[j2] : bf[j2];

    // ---- u-finalize constants (warps 0-3: e = tid>>6, j) ----
    float walast = 0.f, w1last = 0.f, w2last = 0.f, ba_r = 0.f, b1_r = 0.f, b2_r = 0.f;
    if (tid < 128) {
        walast = Wa [j * 65 + 64]; ba_r = ba [j];
        w1last = Wp1[j * 65 + 64]; b1_r = bp1[j];
        w2last = Wp2[j * 65 + 64]; b2_r = bp2[j];
    }
    // ---- y constants: stage-1 warps 6,7; finish warp 5; epilogue warps 6,7 ----
    float woA0 = 0.f, woB0 = 0.f, woA1 = 0.f, woB1 = 0.f;
    if (wid >= 6) {
        woA0 = Wo[lane];      woB0 = Wo[lane + 32];
        woA1 = Wo[64 + lane]; woB1 = Wo[96 + lane];
    }
    float bo0 = 0.f, bo1 = 0.f;
    if (wid == 5 || wid >= 6) { bo0 = bo[0]; bo1 = bo[1]; }

    // ---- preload x + h0 ----
    {
        const float2* xg0 = (const float2*)x + (size_t)b0 * TB;
        const float2* xg1 = (const float2*)x + (size_t)(b0 + 1) * TB;
        for (int i = tid; i < TB; i += 256) { xb[0][i] = xg0[i]; xb[1][i] = xg1[i]; }
    }
    if (tid < 128) hbuf[tid >> 6][j] = h0[(size_t)(b0 + (tid >> 6)) * 64 + j];
    __syncthreads();

    // ---- x-scalar pipeline (u-fin threads), seeded for t=0 ----
    float ampP = 0.f, ctP = 1.f, stP = 0.f;
    if (tid < 128) {
        const int e = tid >> 6;
        float2 xv = xb[e][0];
        float s2 = fmaf(xv.x, xv.x, xv.y * xv.y);
        float ri = rsqrtf(s2);
        bool nz = (s2 > 0.f);
        ampP = nz ? s2 * ri : 0.f;
        ctP  = nz ? xv.x * ri : 1.f;
        stP  = nz ? xv.y * ri : 0.f;
    }

    #pragma unroll 1
    for (int t = 0; t < TB; t++) {
        // ==== seg1: y-stage1 (warps 6-7; hides under ph1 FMA) + ph1 (all) ====
        if (wid >= 6 && t > 0) {
            const int e = wid - 6;
            float ha = hbuf[e][lane], hb = hbuf[e][lane + 32];
            float y0 = fmaf(ha, woA0, hb * woB0);
            float y1 = fmaf(ha, woA1, hb * woB1);
            y0 += __shfl_xor_sync(~0u, y0, 16);
            y1 += __shfl_xor_sync(~0u, y1, 16);
            y0 += __shfl_xor_sync(~0u, y0, 8);
            y1 += __shfl_xor_sync(~0u, y1, 8);
            if (lane < 8) { ypart[e][0][lane] = y0; ypart[e][1][lane] = y1; }
        }
        {
            const float4* h0p = (const float4*)&hbuf[0][s * 16];
            const float4* h1p = (const float4*)&hbuf[1][s * 16];
            float a0 = 0.f, p0 = 0.f, q0 = 0.f, f0 = 0.f, g0 = 0.f;
            float a1 = 0.f, p1 = 0.f, q1 = 0.f, f1 = 0.f, g1 = 0.f;
            #pragma unroll
            for (int r = 0; r < 4; r++) {
                float4 v0 = h0p[r], v1 = h1p[r];
                #pragma unroll
                for (int c = 0; c < 4; c++) {
                    float w_a = wa[4*r+c], w_p = wp1[4*r+c], w_q = wp2[4*r+c];
                    float w_f = wfh[4*r+c], w_g = wgh[4*r+c];
                    float e0 = (c==0)?v0.x:(c==1)?v0.y:(c==2)?v0.z:v0.w;
                    float e1 = (c==0)?v1.x:(c==1)?v1.y:(c==2)?v1.z:v1.w;
                    a0 = fmaf(w_a, e0, a0); a1 = fmaf(w_a, e1, a1);
                    p0 = fmaf(w_p, e0, p0); p1 = fmaf(w_p, e1, p1);
                    q0 = fmaf(w_q, e0, q0); q1 = fmaf(w_q, e1, q1);
                    f0 = fmaf(w_f, e0, f0); f1 = fmaf(w_f, e1, f1);
                    g0 = fmaf(w_g, e0, g0); g1 = fmaf(w_g, e1, g1);
                }
            }
            part[0][0][s][j] = a0;  part[1][0][s][j] = a1;
            part[0][1][s][j] = p0;  part[1][1][s][j] = p1;
            part[0][2][s][j] = q0;  part[1][2][s][j] = q1;
            part[0][3][s][j] = f0;  part[1][3][s][j] = f1;
            part[0][4][s][j] = g0;  part[1][4][s][j] = g1;
        }
        __syncthreads();   // #1

        // ==== seg2: u-finalize (warps 0-3) || y-finish (warp 5) ====
        if (tid < 128) {
            const int e = tid >> 6;
            float sa = (part[e][0][0][j] + part[e][0][1][j])
                     + (part[e][0][2][j] + part[e][0][3][j]);
            float sp = (part[e][1][0][j] + part[e][1][1][j])
                     + (part[e][1][2][j] + part[e][1][3][j]);
            float sq = (part[e][2][0][j] + part[e][2][1][j])
                     + (part[e][2][2][j] + part[e][2][3][j]);
            float av  = tanhmufu(fmaf(ampP, walast, sa + ba_r));
            float p1v = tanhmufu(fmaf(ctP,  w1last, sp + b1_r));
            float p2v = tanhmufu(fmaf(stP,  w2last, sq + b2_r));
            ubuf[e][j] = (av - av * av) * (p1v - p1v * p1v) * (p2v - p2v * p2v);
            // pipeline x-scalars for t+1
            int tn = (t + 1 < TB) ? t + 1 : t;
            float2 xv = xb[e][tn];
            float s2 = fmaf(xv.x, xv.x, xv.y * xv.y);
            float ri = rsqrtf(s2);
            bool nz = (s2 > 0.f);
            ampP = nz ? s2 * ri : 0.f;
            ctP  = nz ? xv.x * ri : 1.f;
            stP  = nz ? xv.y * ri : 0.f;
        } else if (wid == 5 && lane < 4 && t > 0) {
            const int e = lane >> 1, o = lane & 1;
            const float4* yp = (const float4*)&ypart[e][o][0];
            float4 va = yp[0], vb = yp[1];
            float sum = ((va.x + va.y) + (va.z + va.w))
                      + ((vb.x + vb.y) + (vb.z + vb.w));
            out[(((size_t)(b0 + e) * TB) + (t - 1)) * 2 + o] =
                sum + (o ? bo1 : bo0);
        }
        __syncthreads();   // #2

        // ==== seg3: fused f/g u-dot + h-finalize (ALL threads, lane pairs) ====
        {
            const float4* up = (const float4*)&ubuf[e2][0];
            float d0 = 0.f, d1 = 0.f, d2 = 0.f, d3 = 0.f;
            #pragma unroll
            for (int r = 0; r < 4; r++) {
                float4 va = up[4*r+0], vb = up[4*r+1];
                float4 vc = up[4*r+2], vd = up[4*r+3];
                d0 = fmaf(wrow[16*r+ 0], va.x, d0); d1 = fmaf(wrow[16*r+ 1], va.y, d1);
                d2 = fmaf(wrow[16*r+ 2], va.z, d2); d3 = fmaf(wrow[16*r+ 3], va.w, d3);
                d0 = fmaf(wrow[16*r+ 4], vb.x, d0); d1 = fmaf(wrow[16*r+ 5], vb.y, d1);
                d2 = fmaf(wrow[16*r+ 6], vb.z, d2); d3 = fmaf(wrow[16*r+ 7], vb.w, d3);
                d0 = fmaf(wrow[16*r+ 8], vc.x, d0); d1 = fmaf(wrow[16*r+ 9], vc.y, d1);
                d2 = fmaf(wrow[16*r+10], vc.z, d2); d3 = fmaf(wrow[16*r+11], vc.w, d3);
                d0 = fmaf(wrow[16*r+12], vd.x, d0); d1 = fmaf(wrow[16*r+13], vd.y, d1);
                d2 = fmaf(wrow[16*r+14], vd.z, d2); d3 = fmaf(wrow[16*r+15], vd.w, d3);
            }
            const int gidx = 3 + isg;
            float hsum = (part[e2][gidx][0][j2] + part[e2][gidx][1][j2])
                       + (part[e2][gidx][2][j2] + part[e2][gidx][3][j2]);
            float sum = ((d0 + d1) + (d2 + d3)) + (hsum + bias2);
            float val = isg ? tanhmufu(sum) : sigmufu(sum);
            float other = __shfl_xor_sync(~0u, val, 1);
            if (!isg) {
                float fv = val, gv = other;
                float hold = hbuf[e2][j2];
                hbuf[e2][j2] = fmaf(fv, hold - gv, gv);   // f*h + (1-f)*g
            }
        }
        __syncthreads();   // #3
    }

    // ---- epilogue: y for t = TB-1 (full reduction on warps 6-7) ----
    if (wid >= 6) {
        const int e = wid - 6;
        float ha = hbuf[e][lane], hb = hbuf[e][lane + 32];
        float y0 = fmaf(ha, woA0, hb * woB0);
        float y1 = fmaf(ha, woA1, hb * woB1);
        #pragma unroll
        for (int off = 16; off; off >>= 1) {
            y0 += __shfl_xor_sync(~0u, y0, off);
            y1 += __shfl_xor_sync(~0u, y1, off);
        }
        if (lane == 0)
            ((float2*)out)[(size_t)(b0 + e) * TB + (TB - 1)] =
                make_float2(y0 + bo0, y1 + bo1);
    }
}

extern "C" void kernel_launch(void* const* d_in, const int* in_sizes, int n_in,
                              void* d_out, int out_size)
{
    const float* x   = (const float*)d_in[0];
    const float* h0  = (const float*)d_in[1];
    const float* Wa  = (const float*)d_in[2];
    const float* ba  = (const float*)d_in[3];
    const float* Wp1 = (const float*)d_in[4];
    const float* bp1 = (const float*)d_in[5];
    const float* Wp2 = (const float*)d_in[6];
    const float* bp2 = (const float*)d_in[7];
    const float* Wf  = (const float*)d_in[8];
    const float* bf  = (const float*)d_in[9];
    const float* Wg  = (const float*)d_in[10];
    const float* bg  = (const float*)d_in[11];
    const float* Wo  = (const float*)d_in[12];
    const float* bo  = (const float*)d_in[13];
    float* out = (float*)d_out;

    pgjanet_kernel<<<128, 256>>>(x, h0, Wa, ba, Wp1, bp1, Wp2, bp2,
                                 Wf, bf, Wg, bg, Wo, bo, out);
}

// round 16
// speedup vs baseline: 1.0438x; 1.0438x over previous
#include <cuda_runtime.h>

// PGJANET recurrent scan: B=256, T=2048, H=64, O=2.
// R14 base (1253 us: 4 barriers/step, smem partials, scalar FFMA, MUFU
// transcendentals, x-pipeline) + seg-chain shaving:
//  - y-stage1 moved to seg1 (warps 6-7, hidden under ph1 FMA stream)
//  - seg2: warps 4-7 (now idle) prefetch hold + gate-3/4 h-half sums for hfin
//  - y-finish moved to seg2 (warp 5, lanes 0-3)
//  - seg4 is pure h-finalize with a short chain

#define TB 2048

__device__ __forceinline__ float tanhmufu(float v) {
    float r; asm("tanh.approx.f32 %0, %1;" : "=f"(r) : "f"(v)); return r;
}
__device__ __forceinline__ float sigmufu(float v) {
    return fmaf(0.5f, tanhmufu(0.5f * v), 0.5f);
}

__global__ void __launch_bounds__(256, 1)
pgjanet_kernel(const float* __restrict__ x,
               const float* __restrict__ h0,
               const float* __restrict__ Wa,  const float* __restrict__ ba,
               const float* __restrict__ Wp1, const float* __restrict__ bp1,
               const float* __restrict__ Wp2, const float* __restrict__ bp2,
               const float* __restrict__ Wf,  const float* __restrict__ bf,
               const float* __restrict__ Wg,  const float* __restrict__ bg,
               const float* __restrict__ Wo,  const float* __restrict__ bo,
               float* __restrict__ out)
{
    __shared__ __align__(16) float2 xb[2][TB];        // 32 KB
    __shared__ __align__(16) float hbuf[2][64];
    __shared__ __align__(16) float ubuf[2][64];
    __shared__ __align__(16) float part[2][5][4][64]; // [elem][gate][slice][unit]
    __shared__ __align__(16) float ypart[2][2][8];    // [elem][out][8 partials]

    const int tid  = threadIdx.x;
    const int lane = tid & 31;
    const int wid  = tid >> 5;
    const int j    = tid & 63;      // hidden unit
    const int s    = tid >> 6;      // k-slice 0..3
    const int b0   = blockIdx.x * 2;

    // ---- weights in registers (112 floats) ----
    float wa[16], wp1[16], wp2[16], wfh[16], wgh[16], wfu[16], wgu[16];
    {
        const float* A = Wa  + j * 65 + s * 16;
        const float* P = Wp1 + j * 65 + s * 16;
        const float* Q = Wp2 + j * 65 + s * 16;
        const float* F = Wf  + j * 128 + s * 16;
        const float* G = Wg  + j * 128 + s * 16;
        #pragma unroll
        for (int i = 0; i < 16; i++) {
            wa[i]  = A[i];  wp1[i] = P[i];  wp2[i] = Q[i];
            wfh[i] = F[i];  wgh[i] = G[i];
            wfu[i] = F[64 + i]; wgu[i] = G[64 + i];
        }
    }

    // ---- finalize constants ----
    float walast = 0.f, w1last = 0.f, w2last = 0.f, ba_r = 0.f, b1_r = 0.f, b2_r = 0.f;
    if (tid < 128) {                        // u-finalize: (e = tid>>6, j)
        walast = Wa [j * 65 + 64]; ba_r = ba [j];
        w1last = Wp1[j * 65 + 64]; b1_r = bp1[j];
        w2last = Wp2[j * 65 + 64]; b2_r = bp2[j];
    }
    float bf_r = 0.f, bg_r = 0.f;
    if (tid >= 128) { bf_r = bf[j]; bg_r = bg[j]; }   // h-finalize: (e=(tid>>6)&1, j)
    float woA0 = 0.f, woB0 = 0.f, woA1 = 0.f, woB1 = 0.f;
    if (wid >= 6) {                         // y stage-1: warps 6,7 -> elem 0,1
        woA0 = Wo[lane];      woB0 = Wo[lane + 32];
        woA1 = Wo[64 + lane]; woB1 = Wo[96 + lane];
    }
    float bo0 = 0.f, bo1 = 0.f;             // warp 5 (y finish) + warps 6,7 (epilogue)
    if (wid == 5 || wid >= 6) { bo0 = bo[0]; bo1 = bo[1]; }

    // ---- preload x + h0 ----
    {
        const float2* xg0 = (const float2*)x + (size_t)b0 * TB;
        const float2* xg1 = (const float2*)x + (size_t)(b0 + 1) * TB;
        for (int i = tid; i < TB; i += 256) { xb[0][i] = xg0[i]; xb[1][i] = xg1[i]; }
    }
    if (tid < 128) hbuf[tid >> 6][j] = h0[(size_t)(b0 + (tid >> 6)) * 64 + j];
    __syncthreads();

    // ---- x-scalar pipeline registers (u-fin threads), seeded for t=0 ----
    float ampP = 0.f, ctP = 1.f, stP = 0.f;
    if (tid < 128) {
        const int e = tid >> 6;
        float2 xv = xb[e][0];
        float s2 = fmaf(xv.x, xv.x, xv.y * xv.y);
        float ri = rsqrtf(s2);
        bool nz = (s2 > 0.f);
        ampP = nz ? s2 * ri : 0.f;
        ctP  = nz ? xv.x * ri : 1.f;
        stP  = nz ? xv.y * ri : 0.f;
    }

    #pragma unroll 1
    for (int t = 0; t < TB; t++) {
        // ==== seg1: y-stage1 (warps 6-7, hidden) + ph1 partial dots (all) ====
        if (wid >= 6 && t > 0) {
            const int e = wid - 6;
            float ha = hbuf[e][lane], hb = hbuf[e][lane + 32];
            float y0 = fmaf(ha, woA0, hb * woB0);
            float y1 = fmaf(ha, woA1, hb * woB1);
            y0 += __shfl_xor_sync(~0u, y0, 16);
            y1 += __shfl_xor_sync(~0u, y1, 16);
            y0 += __shfl_xor_sync(~0u, y0, 8);
            y1 += __shfl_xor_sync(~0u, y1, 8);
            if (lane < 8) { ypart[e][0][lane] = y0; ypart[e][1][lane] = y1; }
        }
        {
            const float4* h0p = (const float4*)&hbuf[0][s * 16];
            const float4* h1p = (const float4*)&hbuf[1][s * 16];
            float a0 = 0.f, p0 = 0.f, q0 = 0.f, f0 = 0.f, g0 = 0.f;
            float a1 = 0.f, p1 = 0.f, q1 = 0.f, f1 = 0.f, g1 = 0.f;
            #pragma unroll
            for (int r = 0; r < 4; r++) {
                float4 v0 = h0p[r], v1 = h1p[r];
                #pragma unroll
                for (int c = 0; c < 4; c++) {
                    float w_a = wa[4*r+c], w_p = wp1[4*r+c], w_q = wp2[4*r+c];
                    float w_f = wfh[4*r+c], w_g = wgh[4*r+c];
                    float e0 = (c==0)?v0.x:(c==1)?v0.y:(c==2)?v0.z:v0.w;
                    float e1 = (c==0)?v1.x:(c==1)?v1.y:(c==2)?v1.z:v1.w;
                    a0 = fmaf(w_a, e0, a0); a1 = fmaf(w_a, e1, a1);
                    p0 = fmaf(w_p, e0, p0); p1 = fmaf(w_p, e1, p1);
                    q0 = fmaf(w_q, e0, q0); q1 = fmaf(w_q, e1, q1);
                    f0 = fmaf(w_f, e0, f0); f1 = fmaf(w_f, e1, f1);
                    g0 = fmaf(w_g, e0, g0); g1 = fmaf(w_g, e1, g1);
                }
            }
            part[0][0][s][j] = a0;  part[1][0][s][j] = a1;
            part[0][1][s][j] = p0;  part[1][1][s][j] = p1;
            part[0][2][s][j] = q0;  part[1][2][s][j] = q1;
            part[0][3][s][j] = f0;  part[1][3][s][j] = f1;
            part[0][4][s][j] = g0;  part[1][4][s][j] = g1;
        }
        __syncthreads();   // #1

        // ==== seg2: u-finalize (warps 0-3) || hfin prefetch (warps 4-7)
        //            || y-finish (warp 5, lanes 0-3) ====
        float hold_r = 0.f, hsf_r = 0.f, hsg_r = 0.f;   // hfin prefetch regs
        if (tid < 128) {
            const int e = tid >> 6;
            float sa = (part[e][0][0][j] + part[e][0][1][j])
                     + (part[e][0][2][j] + part[e][0][3][j]);
            float sp = (part[e][1][0][j] + part[e][1][1][j])
                     + (part[e][1][2][j] + part[e][1][3][j]);
            float sq = (part[e][2][0][j] + part[e][2][1][j])
                     + (part[e][2][2][j] + part[e][2][3][j]);
            float av  = tanhmufu(fmaf(ampP, walast, sa + ba_r));
            float p1v = tanhmufu(fmaf(ctP,  w1last, sp + b1_r));
            float p2v = tanhmufu(fmaf(stP,  w2last, sq + b2_r));
            ubuf[e][j] = (av - av * av) * (p1v - p1v * p1v) * (p2v - p2v * p2v);
            // pipeline x-scalars for t+1
            int tn = (t + 1 < TB) ? t + 1 : t;
            float2 xv = xb[e][tn];
            float s2 = fmaf(xv.x, xv.x, xv.y * xv.y);
            float ri = rsqrtf(s2);
            bool nz = (s2 > 0.f);
            ampP = nz ? s2 * ri : 0.f;
            ctP  = nz ? xv.x * ri : 1.f;
            stP  = nz ? xv.y * ri : 0.f;
        } else {
            const int e = (tid >> 6) & 1;
            hold_r = hbuf[e][j];
            hsf_r = (part[e][3][0][j] + part[e][3][1][j])
                  + (part[e][3][2][j] + part[e][3][3][j]);
            hsg_r = (part[e][4][0][j] + part[e][4][1][j])
                  + (part[e][4][2][j] + part[e][4][3][j]);
            if (wid == 5 && lane < 4 && t > 0) {
                const int ee = lane >> 1, o = lane & 1;
                const float4* yp = (const float4*)&ypart[ee][o][0];
                float4 va = yp[0], vb = yp[1];
                float sum = ((va.x + va.y) + (va.z + va.w))
                          + ((vb.x + vb.y) + (vb.z + vb.w));
                out[(((size_t)(b0 + ee) * TB) + (t - 1)) * 2 + o] =
                    sum + (o ? bo1 : bo0);
            }
        }
        __syncthreads();   // #2

        // ==== seg3: ph2 f/g u-half partial dots (all threads) ====
        {
            const float4* u0p = (const float4*)&ubuf[0][s * 16];
            const float4* u1p = (const float4*)&ubuf[1][s * 16];
            float cf0 = 0.f, cg0 = 0.f, cf1 = 0.f, cg1 = 0.f;
            #pragma unroll
            for (int r = 0; r < 4; r++) {
                float4 v0 = u0p[r], v1 = u1p[r];
                #pragma unroll
                for (int c = 0; c < 4; c++) {
                    float w_f = wfu[4*r+c], w_g = wgu[4*r+c];
                    float e0 = (c==0)?v0.x:(c==1)?v0.y:(c==2)?v0.z:v0.w;
                    float e1 = (c==0)?v1.x:(c==1)?v1.y:(c==2)?v1.z:v1.w;
                    cf0 = fmaf(w_f, e0, cf0); cf1 = fmaf(w_f, e1, cf1);
                    cg0 = fmaf(w_g, e0, cg0); cg1 = fmaf(w_g, e1, cg1);
                }
            }
            part[0][0][s][j] = cf0;  part[1][0][s][j] = cf1;
            part[0][1][s][j] = cg0;  part[1][1][s][j] = cg1;
        }
        __syncthreads();   // #3

        // ==== seg4: h-finalize only (warps 4-7; short chain) ====
        if (tid >= 128) {
            const int e = (tid >> 6) & 1;
            float sf = ((part[e][0][0][j] + part[e][0][1][j])
                      + (part[e][0][2][j] + part[e][0][3][j])) + (hsf_r + bf_r);
            float sg = ((part[e][1][0][j] + part[e][1][1][j])
                      + (part[e][1][2][j] + part[e][1][3][j])) + (hsg_r + bg_r);
            float f = sigmufu(sf);
            float g = tanhmufu(sg);
            hbuf[e][j] = fmaf(f, hold_r - g, g);   // f*h + (1-f)*g
        }
        __syncthreads();   // #4
    }

    // ---- epilogue: y for t = TB-1 (full reduction on warps 6-7) ----
    if (wid >= 6) {
        const int e = wid - 6;
        float ha = hbuf[e][lane], hb = hbuf[e][lane + 32];
        float y0 = fmaf(ha, woA0, hb * woB0);
        float y1 = fmaf(ha, woA1, hb * woB1);
        #pragma unroll
        for (int off = 16; off; off >>= 1) {
            y0 += __shfl_xor_sync(~0u, y0, off);
            y1 += __shfl_xor_sync(~0u, y1, off);
        }
        if (lane == 0)
            ((float2*)out)[(size_t)(b0 + e) * TB + (TB - 1)] =
                make_float2(y0 + bo0, y1 + bo1);
    }
}

extern "C" void kernel_launch(void* const* d_in, const int* in_sizes, int n_in,
                              void* d_out, int out_size)
{
    const float* x   = (const float*)d_in[0];
    const float* h0  = (const float*)d_in[1];
    const float* Wa  = (const float*)d_in[2];
    const float* ba  = (const float*)d_in[3];
    const float* Wp1 = (const float*)d_in[4];
    const float* bp1 = (const float*)d_in[5];
    const float* Wp2 = (const float*)d_in[6];
    const float* bp2 = (const float*)d_in[7];
    const float* Wf  = (const float*)d_in[8];
    const float* bf  = (const float*)d_in[9];
    const float* Wg  = (const float*)d_in[10];
    const float* bg  = (const float*)d_in[11];
    const float* Wo  = (const float*)d_in[12];
    const float* bo  = (const float*)d_in[13];
    float* out = (float*)d_out;

    pgjanet_kernel<<<128, 256>>>(x, h0, Wa, ba, Wp1, bp1, Wp2, bp2,
                                 Wf, bf, Wg, bg, Wo, bo, out);
}

// round 17
// speedup vs baseline: 1.0994x; 1.0533x over previous
#include <cuda_runtime.h>
#include <cuda_fp16.h>

// PGJANET recurrent scan: B=256, T=2048, H=64, O=2.
// R14 base (1253 us: 4 barriers/step, smem partials, MUFU transcendentals,
// x-pipeline, y split across seg2/seg4). SINGLE change: the a/p1/p2 h-dots
// use packed HFMA2 (fp16, 2 MACs/issue) — these gates are damped ~16x through
// u = prod(t - t^2), so fp16 accumulation error (~6e-4 pre-act) injects only
// ~4e-5 into u. f/g dots, partials, reductions, finalize all stay fp32.
// h is mirrored as half2 (written by h-finalize).

#define TB 2048

__device__ __forceinline__ float tanhmufu(float v) {
    float r; asm("tanh.approx.f32 %0, %1;" : "=f"(r) : "f"(v)); return r;
}
__device__ __forceinline__ float sigmufu(float v) {
    return fmaf(0.5f, tanhmufu(0.5f * v), 0.5f);
}

__global__ void __launch_bounds__(256, 1)
pgjanet_kernel(const float* __restrict__ x,
               const float* __restrict__ h0,
               const float* __restrict__ Wa,  const float* __restrict__ ba,
               const float* __restrict__ Wp1, const float* __restrict__ bp1,
               const float* __restrict__ Wp2, const float* __restrict__ bp2,
               const float* __restrict__ Wf,  const float* __restrict__ bf,
               const float* __restrict__ Wg,  const float* __restrict__ bg,
               const float* __restrict__ Wo,  const float* __restrict__ bo,
               float* __restrict__ out)
{
    __shared__ __align__(16) float2 xb[2][TB];        // 32 KB
    __shared__ __align__(16) float hbuf[2][64];       // fp32 h
    __shared__ __align__(16) __half hbufh[2][64];     // fp16 mirror of h
    __shared__ __align__(16) float ubuf[2][64];
    __shared__ __align__(16) float part[2][5][4][64]; // [elem][gate][slice][unit]
    __shared__ __align__(16) float ypart[2][2][8];    // [elem][out][8 partials]

    const int tid  = threadIdx.x;
    const int lane = tid & 31;
    const int wid  = tid >> 5;
    const int j    = tid & 63;      // hidden unit
    const int s    = tid >> 6;      // k-slice 0..3
    const int b0   = blockIdx.x * 2;

    // ---- weights: a/p1/p2 packed half2 (k-pairs); f/g fp32 ----
    half2 wah[8], wp1h[8], wp2h[8];
    float wfh[16], wgh[16], wfu[16], wgu[16];
    {
        const float* A = Wa  + j * 65 + s * 16;
        const float* P = Wp1 + j * 65 + s * 16;
        const float* Q = Wp2 + j * 65 + s * 16;
        #pragma unroll
        for (int i = 0; i < 8; i++) {
            wah[i]  = __floats2half2_rn(A[2*i], A[2*i+1]);
            wp1h[i] = __floats2half2_rn(P[2*i], P[2*i+1]);
            wp2h[i] = __floats2half2_rn(Q[2*i], Q[2*i+1]);
        }
        const float* F = Wf + j * 128 + s * 16;
        const float* G = Wg + j * 128 + s * 16;
        #pragma unroll
        for (int i = 0; i < 16; i++) {
            wfh[i] = F[i];  wgh[i] = G[i];
            wfu[i] = F[64 + i]; wgu[i] = G[64 + i];
        }
    }

    // ---- finalize constants ----
    float walast = 0.f, w1last = 0.f, w2last = 0.f, ba_r = 0.f, b1_r = 0.f, b2_r = 0.f;
    if (tid < 128) {                        // u-finalize: (e = tid>>6, j)
        walast = Wa [j * 65 + 64]; ba_r = ba [j];
        w1last = Wp1[j * 65 + 64]; b1_r = bp1[j];
        w2last = Wp2[j * 65 + 64]; b2_r = bp2[j];
    }
    float bf_r = 0.f, bg_r = 0.f;
    if (tid >= 128) { bf_r = bf[j]; bg_r = bg[j]; }   // h-finalize: (e=(tid>>6)&1, j)
    float woA0 = 0.f, woB0 = 0.f, woA1 = 0.f, woB1 = 0.f;
    if (wid >= 6) {                         // y stage-1: warps 6,7 -> elem 0,1
        woA0 = Wo[lane];      woB0 = Wo[lane + 32];
        woA1 = Wo[64 + lane]; woB1 = Wo[96 + lane];
    }
    float bo0 = 0.f, bo1 = 0.f;             // warp 0 (y finish) + warps 6,7 (epilogue)
    if (wid == 0 || wid >= 6) { bo0 = bo[0]; bo1 = bo[1]; }

    // ---- preload x + h0 (fp32 + fp16 mirror) ----
    {
        const float2* xg0 = (const float2*)x + (size_t)b0 * TB;
        const float2* xg1 = (const float2*)x + (size_t)(b0 + 1) * TB;
        for (int i = tid; i < TB; i += 256) { xb[0][i] = xg0[i]; xb[1][i] = xg1[i]; }
    }
    if (tid < 128) {
        float hv = h0[(size_t)(b0 + (tid >> 6)) * 64 + j];
        hbuf[tid >> 6][j]  = hv;
        hbufh[tid >> 6][j] = __float2half_rn(hv);
    }
    __syncthreads();

    // ---- x-scalar pipeline registers (u-fin threads), seeded for t=0 ----
    float ampP = 0.f, ctP = 1.f, stP = 0.f;
    if (tid < 128) {
        const int e = tid >> 6;
        float2 xv = xb[e][0];
        float s2 = fmaf(xv.x, xv.x, xv.y * xv.y);
        float ri = rsqrtf(s2);
        bool nz = (s2 > 0.f);
        ampP = nz ? s2 * ri : 0.f;
        ctP  = nz ? xv.x * ri : 1.f;
        stP  = nz ? xv.y * ri : 0.f;
    }

    #pragma unroll 1
    for (int t = 0; t < TB; t++) {
        // ==== phase 1: a/p1/p2 (HFMA2) + f/g h-half (FFMA) partial dots ====
        {
            // fp16 h slices (16 halfs = 2 uint4 per elem)
            const uint4* hh0 = (const uint4*)&hbufh[0][s * 16];
            const uint4* hh1 = (const uint4*)&hbufh[1][s * 16];
            uint4 u0a = hh0[0], u0b = hh0[1];
            uint4 u1a = hh1[0], u1b = hh1[1];
            const half2* hp0 = (const half2*)&u0a;   // 4 + 4 half2
            const half2* hp1 = (const half2*)&u1a;
            half2 A0 = __float2half2_rn(0.f), P0 = A0, Q0 = A0;
            half2 A1 = A0, P1 = A0, Q1 = A0;
            #pragma unroll
            for (int r = 0; r < 4; r++) {
                half2 v0 = hp0[r], v1 = hp1[r];
                A0 = __hfma2(wah[r],  v0, A0);  A1 = __hfma2(wah[r],  v1, A1);
                P0 = __hfma2(wp1h[r], v0, P0);  P1 = __hfma2(wp1h[r], v1, P1);
                Q0 = __hfma2(wp2h[r], v0, Q0);  Q1 = __hfma2(wp2h[r], v1, Q1);
            }
            {
                const half2* hq0 = (const half2*)&u0b;
                const half2* hq1 = (const half2*)&u1b;
                #pragma unroll
                for (int r = 0; r < 4; r++) {
                    half2 v0 = hq0[r], v1 = hq1[r];
                    A0 = __hfma2(wah[4+r],  v0, A0);  A1 = __hfma2(wah[4+r],  v1, A1);
                    P0 = __hfma2(wp1h[4+r], v0, P0);  P1 = __hfma2(wp1h[4+r], v1, P1);
                    Q0 = __hfma2(wp2h[4+r], v0, Q0);  Q1 = __hfma2(wp2h[4+r], v1, Q1);
                }
            }
            // fp32 f/g dots over fp32 h
            const float4* h0p = (const float4*)&hbuf[0][s * 16];
            const float4* h1p = (const float4*)&hbuf[1][s * 16];
            float f0 = 0.f, g0 = 0.f, f1 = 0.f, g1 = 0.f;
            #pragma unroll
            for (int r = 0; r < 4; r++) {
                float4 v0 = h0p[r], v1 = h1p[r];
                #pragma unroll
                for (int c = 0; c < 4; c++) {
                    float w_f = wfh[4*r+c], w_g = wgh[4*r+c];
                    float e0 = (c==0)?v0.x:(c==1)?v0.y:(c==2)?v0.z:v0.w;
                    float e1 = (c==0)?v1.x:(c==1)?v1.y:(c==2)?v1.z:v1.w;
                    f0 = fmaf(w_f, e0, f0); f1 = fmaf(w_f, e1, f1);
                    g0 = fmaf(w_g, e0, g0); g1 = fmaf(w_g, e1, g1);
                }
            }
            part[0][0][s][j] = __low2float(A0) + __high2float(A0);
            part[1][0][s][j] = __low2float(A1) + __high2float(A1);
            part[0][1][s][j] = __low2float(P0) + __high2float(P0);
            part[1][1][s][j] = __low2float(P1) + __high2float(P1);
            part[0][2][s][j] = __low2float(Q0) + __high2float(Q0);
            part[1][2][s][j] = __low2float(Q1) + __high2float(Q1);
            part[0][3][s][j] = f0;  part[1][3][s][j] = f1;
            part[0][4][s][j] = g0;  part[1][4][s][j] = g1;
        }
        __syncthreads();   // #1

        // ==== seg2: u-finalize (warps 0-3) || y stage-1 (warps 6-7) ====
        if (tid < 128) {
            const int e = tid >> 6;
            float sa = (part[e][0][0][j] + part[e][0][1][j])
                     + (part[e][0][2][j] + part[e][0][3][j]);
            float sp = (part[e][1][0][j] + part[e][1][1][j])
                     + (part[e][1][2][j] + part[e][1][3][j]);
            float sq = (part[e][2][0][j] + part[e][2][1][j])
                     + (part[e][2][2][j] + part[e][2][3][j]);
            float av  = tanhmufu(fmaf(ampP, walast, sa + ba_r));
            float p1v = tanhmufu(fmaf(ctP,  w1last, sp + b1_r));
            float p2v = tanhmufu(fmaf(stP,  w2last, sq + b2_r));
            ubuf[e][j] = (av - av * av) * (p1v - p1v * p1v) * (p2v - p2v * p2v);
            // pipeline x-scalars for t+1
            int tn = (t + 1 < TB) ? t + 1 : t;
            float2 xv = xb[e][tn];
            float s2 = fmaf(xv.x, xv.x, xv.y * xv.y);
            float ri = rsqrtf(s2);
            bool nz = (s2 > 0.f);
            ampP = nz ? s2 * ri : 0.f;
            ctP  = nz ? xv.x * ri : 1.f;
            stP  = nz ? xv.y * ri : 0.f;
        } else if (wid >= 6 && t > 0) {
            const int e = wid - 6;
            float ha = hbuf[e][lane], hb = hbuf[e][lane + 32];
            float y0 = fmaf(ha, woA0, hb * woB0);
            float y1 = fmaf(ha, woA1, hb * woB1);
            y0 += __shfl_xor_sync(~0u, y0, 16);
            y1 += __shfl_xor_sync(~0u, y1, 16);
            y0 += __shfl_xor_sync(~0u, y0, 8);
            y1 += __shfl_xor_sync(~0u, y1, 8);
            if (lane < 8) { ypart[e][0][lane] = y0; ypart[e][1][lane] = y1; }
        }
        __syncthreads();   // #2

        // ==== phase 2: f/g u-half partial dots (fp32, both elems) ====
        {
            const float4* u0p = (const float4*)&ubuf[0][s * 16];
            const float4* u1p = (const float4*)&ubuf[1][s * 16];
            float cf0 = 0.f, cg0 = 0.f, cf1 = 0.f, cg1 = 0.f;
            #pragma unroll
            for (int r = 0; r < 4; r++) {
                float4 v0 = u0p[r], v1 = u1p[r];
                #pragma unroll
                for (int c = 0; c < 4; c++) {
                    float w_f = wfu[4*r+c], w_g = wgu[4*r+c];
                    float e0 = (c==0)?v0.x:(c==1)?v0.y:(c==2)?v0.z:v0.w;
                    float e1 = (c==0)?v1.x:(c==1)?v1.y:(c==2)?v1.z:v1.w;
                    cf0 = fmaf(w_f, e0, cf0); cf1 = fmaf(w_f, e1, cf1);
                    cg0 = fmaf(w_g, e0, cg0); cg1 = fmaf(w_g, e1, cg1);
                }
            }
            part[0][0][s][j] = cf0;  part[1][0][s][j] = cf1;
            part[0][1][s][j] = cg0;  part[1][1][s][j] = cg1;
        }
        __syncthreads();   // #3

        // ==== seg4: h-finalize (warps 4-7) || y finish (warp 0, lanes 0-3) ====
        if (tid >= 128) {
            const int e = (tid >> 6) & 1;
            float sf = ((part[e][0][0][j] + part[e][0][1][j])
                      + (part[e][0][2][j] + part[e][0][3][j]))
                     + ((part[e][3][0][j] + part[e][3][1][j])
                      + (part[e][3][2][j] + part[e][3][3][j]));
            float sg = ((part[e][1][0][j] + part[e][1][1][j])
                      + (part[e][1][2][j] + part[e][1][3][j]))
                     + ((part[e][4][0][j] + part[e][4][1][j])
                      + (part[e][4][2][j] + part[e][4][3][j]));
            float f = sigmufu(sf + bf_r);
            float g = tanhmufu(sg + bg_r);
            float hold = hbuf[e][j];
            float hn = fmaf(f, hold - g, g);   // f*h + (1-f)*g
            hbuf[e][j]  = hn;
            hbufh[e][j] = __float2half_rn(hn);
        } else if (wid == 0 && lane < 4 && t > 0) {
            const int e = lane >> 1, o = lane & 1;
            const float4* yp = (const float4*)&ypart[e][o][0];
            float4 va = yp[0], vb = yp[1];
            float sum = ((va.x + va.y) + (va.z + va.w))
                      + ((vb.x + vb.y) + (vb.z + vb.w));
            out[(((size_t)(b0 + e) * TB) + (t - 1)) * 2 + o] =
                sum + (o ? bo1 : bo0);
        }
        __syncthreads();   // #4
    }

    // ---- epilogue: y for t = TB-1 (full reduction on warps 6-7) ----
    if (wid >= 6) {
        const int e = wid - 6;
        float ha = hbuf[e][lane], hb = hbuf[e][lane + 32];
        float y0 = fmaf(ha, woA0, hb * woB0);
        float y1 = fmaf(ha, woA1, hb * woB1);
        #pragma unroll
        for (int off = 16; off; off >>= 1) {
            y0 += __shfl_xor_sync(~0u, y0, off);
            y1 += __shfl_xor_sync(~0u, y1, off);
        }
        if (lane == 0)
            ((float2*)out)[(size_t)(b0 + e) * TB + (TB - 1)] =
                make_float2(y0 + bo0, y1 + bo1);
    }
}

extern "C" void kernel_launch(void* const* d_in, const int* in_sizes, int n_in,
                              void* d_out, int out_size)
{
    const float* x   = (const float*)d_in[0];
    const float* h0  = (const float*)d_in[1];
    const float* Wa  = (const float*)d_in[2];
    const float* ba  = (const float*)d_in[3];
    const float* Wp1 = (const float*)d_in[4];
    const float* bp1 = (const float*)d_in[5];
    const float* Wp2 = (const float*)d_in[6];
    const float* bp2 = (const float*)d_in[7];
    const float* Wf  = (const float*)d_in[8];
    const float* bf  = (const float*)d_in[9];
    const float* Wg  = (const float*)d_in[10];
    const float* bg  = (const float*)d_in[11];
    const float* Wo  = (const float*)d_in[12];
    const float* bo  = (const float*)d_in[13];
    float* out = (float*)d_out;

    pgjanet_kernel<<<128, 256>>>(x, h0, Wa, ba, Wp1, bp1, Wp2, bp2,
                                 Wf, bf, Wg, bg, Wo, bo, out);
}